// round 1
// baseline (speedup 1.0000x reference)
#include <cuda_runtime.h>
#include <math.h>

#define N_NODES 50000
#define N_EDGES 500000
#define HID 256
#define LAYERS 15
#define EPS 1e-5f

// ---------------- device scratch (no allocs allowed) ----------------
__device__ float g_h[N_NODES * HID];
__device__ float g_agg[N_NODES * HID];
__device__ float g_out[N_NODES * HID];
__device__ float g_P[N_NODES * HID];
__device__ float g_Q[N_NODES * HID];
__device__ int   g_deg[N_NODES];
__device__ int   g_rowptr[N_NODES + 1];
__device__ int   g_cursor[N_NODES];
__device__ int   g_srcl[N_EDGES];
__device__ double g_sumd[HID];
__device__ double g_sqd[HID];
__device__ float g_scale[HID];
__device__ float g_shift[HID];

// ---------------- CSR build ----------------
__global__ void zero_int_kernel() {
    int i = blockIdx.x * blockDim.x + threadIdx.x;
    if (i < N_NODES) { g_deg[i] = 0; g_cursor[i] = 0; }
}

__global__ void count_kernel(const int* __restrict__ dst) {
    int e = blockIdx.x * blockDim.x + threadIdx.x;
    if (e < N_EDGES) atomicAdd(&g_deg[dst[e]], 1);
}

__global__ void scan_kernel() {  // single block, 1024 threads
    __shared__ int s[1024];
    const int CH = (N_NODES + 1023) / 1024;  // 49
    int t = threadIdx.x;
    int start = t * CH;
    int end = start + CH; if (end > N_NODES) end = N_NODES;
    if (start > N_NODES) start = N_NODES;
    int sum = 0;
    for (int i = start; i < end; i++) sum += g_deg[i];
    s[t] = sum;
    __syncthreads();
    for (int off = 1; off < 1024; off <<= 1) {
        int v = 0;
        if (t >= off) v = s[t - off];
        __syncthreads();
        if (t >= off) s[t] += v;
        __syncthreads();
    }
    int run = (t == 0) ? 0 : s[t - 1];
    for (int i = start; i < end; i++) { g_rowptr[i] = run; run += g_deg[i]; }
    if (t == 1023) g_rowptr[N_NODES] = run;  // == N_EDGES
}

__global__ void fill_kernel(const int* __restrict__ src, const int* __restrict__ dst) {
    int e = blockIdx.x * blockDim.x + threadIdx.x;
    if (e < N_EDGES) {
        int d = dst[e];
        int p = atomicAdd(&g_cursor[d], 1);
        g_srcl[g_rowptr[d] + p] = src[e];
    }
}

// ---------------- input fc: h = x @ W_in^T ----------------
__global__ void input_kernel(const float* __restrict__ x, const float* __restrict__ Win) {
    int idx = blockIdx.x * blockDim.x + threadIdx.x;  // float4 units
    if (idx >= N_NODES * 64) return;
    int node = idx >> 6;
    int c = (idx & 63) * 4;
    float x0 = x[node * 2 + 0];
    float x1 = x[node * 2 + 1];
    float4 o;
    o.x = x0 * Win[(c + 0) * 2] + x1 * Win[(c + 0) * 2 + 1];
    o.y = x0 * Win[(c + 1) * 2] + x1 * Win[(c + 1) * 2 + 1];
    o.z = x0 * Win[(c + 2) * 2] + x1 * Win[(c + 2) * 2 + 1];
    o.w = x0 * Win[(c + 3) * 2] + x1 * Win[(c + 3) * 2 + 1];
    ((float4*)g_h)[idx] = o;
}

// ---------------- aggregation: warp per node, CSR gather-sum ----------------
__global__ void agg_kernel() {
    int gt = blockIdx.x * blockDim.x + threadIdx.x;
    int node = gt >> 5;
    int lane = gt & 31;
    if (node >= N_NODES) return;
    int beg = g_rowptr[node], end = g_rowptr[node + 1];
    float4 a0 = make_float4(0.f, 0.f, 0.f, 0.f);
    float4 a1 = make_float4(0.f, 0.f, 0.f, 0.f);
    const float4* hp = (const float4*)g_h;
    for (int i = beg; i < end; i++) {
        int s = g_srcl[i];
        float4 x0 = hp[s * 64 + lane * 2];
        float4 x1 = hp[s * 64 + lane * 2 + 1];
        a0.x += x0.x; a0.y += x0.y; a0.z += x0.z; a0.w += x0.w;
        a1.x += x1.x; a1.y += x1.y; a1.z += x1.z; a1.w += x1.w;
    }
    ((float4*)g_agg)[node * 64 + lane * 2] = a0;
    ((float4*)g_agg)[node * 64 + lane * 2 + 1] = a1;
}

// ---------------- SGEMM: C[M,256] = A1@W1^T (+ A2@W2^T) (+ bias) ----------------
// A row-major [M,256]; W rows: W[n*ldw + k] (k over 0..255)
__global__ void __launch_bounds__(256) sgemm_kernel(
    const float* __restrict__ A1, const float* __restrict__ W1,
    const float* __restrict__ A2, const float* __restrict__ W2,
    const float* __restrict__ bias, float* __restrict__ C, int ldw)
{
    __shared__ float As[16][128];
    __shared__ float Bs[16][64];
    int tid = threadIdx.x;
    int bm = blockIdx.x, bn = blockIdx.y;
    int tmi = tid >> 4;      // 0..15 (row group of 8)
    int tni = tid & 15;      // 0..15 (col group of 4)
    float acc[8][4];
#pragma unroll
    for (int i = 0; i < 8; i++)
#pragma unroll
        for (int j = 0; j < 4; j++) acc[i][j] = 0.f;

    int rowC0 = bm * 128;

    for (int pass = 0; pass < 2; pass++) {
        const float* A = pass ? A2 : A1;
        const float* W = pass ? W2 : W1;
        if (!A) break;
        for (int kc = 0; kc < HID; kc += 16) {
#pragma unroll
            for (int it = 0; it < 2; it++) {
                int v = it * 256 + tid;   // 0..511
                int m = v >> 2;
                int k4 = (v & 3) * 4;
                int row = rowC0 + m;
                float4 f = make_float4(0.f, 0.f, 0.f, 0.f);
                if (row < N_NODES) f = *(const float4*)&A[row * HID + kc + k4];
                As[k4 + 0][m] = f.x; As[k4 + 1][m] = f.y;
                As[k4 + 2][m] = f.z; As[k4 + 3][m] = f.w;
            }
            {
                int n = tid >> 2;
                int k4 = (tid & 3) * 4;
                float4 f = *(const float4*)&W[(bn * 64 + n) * ldw + kc + k4];
                Bs[k4 + 0][n] = f.x; Bs[k4 + 1][n] = f.y;
                Bs[k4 + 2][n] = f.z; Bs[k4 + 3][n] = f.w;
            }
            __syncthreads();
#pragma unroll
            for (int k = 0; k < 16; k++) {
                float4 a0 = *(float4*)&As[k][tmi * 8];
                float4 a1 = *(float4*)&As[k][tmi * 8 + 4];
                float4 b = *(float4*)&Bs[k][tni * 4];
                float a[8] = {a0.x, a0.y, a0.z, a0.w, a1.x, a1.y, a1.z, a1.w};
                float bb[4] = {b.x, b.y, b.z, b.w};
#pragma unroll
                for (int i = 0; i < 8; i++)
#pragma unroll
                    for (int j = 0; j < 4; j++) acc[i][j] += a[i] * bb[j];
            }
            __syncthreads();
        }
    }
    int col0 = bn * 64 + tni * 4;
    float4 bv = make_float4(0.f, 0.f, 0.f, 0.f);
    if (bias) bv = *(const float4*)&bias[col0];
#pragma unroll
    for (int i = 0; i < 8; i++) {
        int row = rowC0 + tmi * 8 + i;
        if (row < N_NODES) {
            float4 o;
            o.x = acc[i][0] + bv.x; o.y = acc[i][1] + bv.y;
            o.z = acc[i][2] + bv.z; o.w = acc[i][3] + bv.w;
            *(float4*)&C[row * HID + col0] = o;
        }
    }
}

// ---------------- BN stats ----------------
__global__ void zstats_kernel() {
    int c = threadIdx.x;
    g_sumd[c] = 0.0; g_sqd[c] = 0.0;
}

__global__ void stats_kernel() {
    int c = threadIdx.x;
    int r0 = blockIdx.x * 250;
    int r1 = r0 + 250; if (r1 > N_NODES) r1 = N_NODES;
    float s = 0.f, q = 0.f;
    for (int r = r0; r < r1; r++) {
        float v = g_out[r * HID + c];
        s += v; q += v * v;
    }
    atomicAdd(&g_sumd[c], (double)s);
    atomicAdd(&g_sqd[c], (double)q);
}

__global__ void bnfinal_kernel(const float* __restrict__ gamma, const float* __restrict__ beta) {
    int c = threadIdx.x;
    float mean = (float)(g_sumd[c] / (double)N_NODES);
    float var = (float)(g_sqd[c] / (double)N_NODES) - mean * mean;
    float rstd = rsqrtf(var + EPS);
    float sc = rstd * gamma[c];
    g_scale[c] = sc;
    g_shift[c] = beta[c] - mean * sc;
}

__global__ void bnapply_kernel() {
    int idx = blockIdx.x * blockDim.x + threadIdx.x;  // float4 units
    if (idx >= N_NODES * 64) return;
    int c4 = idx & 63;
    float4 o = ((const float4*)g_out)[idx];
    float4 h = ((float4*)g_h)[idx];
    float4 sc = ((const float4*)g_scale)[c4];
    float4 sh = ((const float4*)g_shift)[c4];
    h.x += fmaxf(o.x * sc.x + sh.x, 0.f);
    h.y += fmaxf(o.y * sc.y + sh.y, 0.f);
    h.z += fmaxf(o.z * sc.z + sh.z, 0.f);
    h.w += fmaxf(o.w * sc.w + sh.w, 0.f);
    ((float4*)g_h)[idx] = h;
}

// ---------------- fused edge MLP ----------------
// z1 = relu(P[src] + Q[dst])  (b1 folded into P)
// z2 = relu(z1 @ W2^T + b2) ; out = sigmoid(z2 @ W3^T + b3)
#define ETM 64
#define Z1_STRIDE 260
#define W2_STRIDE 264
#define SMEM_EDGE ((ETM * Z1_STRIDE + 32 * W2_STRIDE) * 4 + 2 * ETM * 4)

__global__ void __launch_bounds__(256) edge_kernel(
    const int* __restrict__ src, const int* __restrict__ dst,
    const float* __restrict__ W2, const float* __restrict__ b2,
    const float* __restrict__ W3, const float* __restrict__ b3,
    float* __restrict__ out)
{
    extern __shared__ float smem[];
    float* z1 = smem;                       // [ETM][Z1_STRIDE]
    float* w2 = z1 + ETM * Z1_STRIDE;       // [32][W2_STRIDE]
    int* se = (int*)(w2 + 32 * W2_STRIDE);  // [ETM]
    int* de = se + ETM;                     // [ETM]

    int tid = threadIdx.x;
    int eb = blockIdx.x * ETM;
    if (tid < ETM) {
        int e = eb + tid;
        se[tid] = (e < N_EDGES) ? src[e] : 0;
        de[tid] = (e < N_EDGES) ? dst[e] : 0;
    }
    __syncthreads();

    // phase A: build z1 tile (relu(P[s]+Q[d]))
    const float4* Pp = (const float4*)g_P;
    const float4* Qp = (const float4*)g_Q;
#pragma unroll
    for (int j = 0; j < 16; j++) {
        int fid = tid + j * 256;       // 0..4095 float4 units
        int i = fid >> 6;
        int c4 = fid & 63;
        float4 p = Pp[se[i] * 64 + c4];
        float4 q = Qp[de[i] * 64 + c4];
        float4 v;
        v.x = fmaxf(p.x + q.x, 0.f);
        v.y = fmaxf(p.y + q.y, 0.f);
        v.z = fmaxf(p.z + q.z, 0.f);
        v.w = fmaxf(p.w + q.w, 0.f);
        *(float4*)&z1[i * Z1_STRIDE + c4 * 4] = v;
    }
    __syncthreads();

    // phase B: z2 = z1 @ W2^T, tiled over K
    int tmi = tid >> 5;   // warp id 0..7 -> rows tmi*8..+7
    int tni = tid & 31;   // lane -> cols {tni + 32*j}
    float acc[8][8];
#pragma unroll
    for (int i = 0; i < 8; i++)
#pragma unroll
        for (int j = 0; j < 8; j++) acc[i][j] = 0.f;

    for (int kc = 0; kc < HID; kc += 32) {
        // stage W2 tile [k 0..31][n 0..255] transposed
#pragma unroll
        for (int j = 0; j < 8; j++) {
            float4 w = *(const float4*)&W2[tid * HID + kc + j * 4];
            w2[(j * 4 + 0) * W2_STRIDE + tid] = w.x;
            w2[(j * 4 + 1) * W2_STRIDE + tid] = w.y;
            w2[(j * 4 + 2) * W2_STRIDE + tid] = w.z;
            w2[(j * 4 + 3) * W2_STRIDE + tid] = w.w;
        }
        __syncthreads();
#pragma unroll
        for (int k = 0; k < 32; k++) {
            float a[8], b[8];
#pragma unroll
            for (int i = 0; i < 8; i++) a[i] = z1[(tmi * 8 + i) * Z1_STRIDE + kc + k];
#pragma unroll
            for (int j = 0; j < 8; j++) b[j] = w2[k * W2_STRIDE + tni + 32 * j];
#pragma unroll
            for (int i = 0; i < 8; i++)
#pragma unroll
                for (int j = 0; j < 8; j++) acc[i][j] += a[i] * b[j];
        }
        __syncthreads();
    }

    // phase C: relu(z2 + b2) dot W3, warp-reduce, sigmoid
    float b2r[8], w3r[8];
#pragma unroll
    for (int j = 0; j < 8; j++) {
        b2r[j] = b2[tni + 32 * j];
        w3r[j] = W3[tni + 32 * j];
    }
    float res[8];
#pragma unroll
    for (int i = 0; i < 8; i++) {
        float p = 0.f;
#pragma unroll
        for (int j = 0; j < 8; j++) p += fmaxf(acc[i][j] + b2r[j], 0.f) * w3r[j];
        res[i] = p;
    }
#pragma unroll
    for (int off = 16; off > 0; off >>= 1)
#pragma unroll
        for (int i = 0; i < 8; i++)
            res[i] += __shfl_xor_sync(0xffffffffu, res[i], off);
    if (tni == 0) {
        float bb3 = b3[0];
#pragma unroll
        for (int i = 0; i < 8; i++) {
            int e = eb + tmi * 8 + i;
            if (e < N_EDGES) out[e] = 1.f / (1.f + expf(-(res[i] + bb3)));
        }
    }
}

// ---------------- launcher ----------------
extern "C" void kernel_launch(void* const* d_in, const int* in_sizes, int n_in,
                              void* d_out, int out_size) {
    const float* x     = (const float*)d_in[0];
    const int*   ei    = (const int*)d_in[1];
    const float* Win   = (const float*)d_in[2];
    const float* Wrel  = (const float*)d_in[3];
    const float* brel  = (const float*)d_in[4];
    const float* Wroot = (const float*)d_in[5];
    const float* gamma = (const float*)d_in[6];
    const float* beta  = (const float*)d_in[7];
    const float* W1    = (const float*)d_in[8];
    const float* b1    = (const float*)d_in[9];
    const float* W2    = (const float*)d_in[10];
    const float* b2    = (const float*)d_in[11];
    const float* W3    = (const float*)d_in[12];
    const float* b3    = (const float*)d_in[13];
    float* out = (float*)d_out;
    const int* src = ei;
    const int* dst = ei + N_EDGES;

    float *p_agg, *p_h, *p_out, *p_P, *p_Q;
    cudaGetSymbolAddress((void**)&p_agg, g_agg);
    cudaGetSymbolAddress((void**)&p_h, g_h);
    cudaGetSymbolAddress((void**)&p_out, g_out);
    cudaGetSymbolAddress((void**)&p_P, g_P);
    cudaGetSymbolAddress((void**)&p_Q, g_Q);

    cudaFuncSetAttribute(edge_kernel, cudaFuncAttributeMaxDynamicSharedMemorySize, SMEM_EDGE);

    // CSR build
    zero_int_kernel<<<(N_NODES + 255) / 256, 256>>>();
    count_kernel<<<(N_EDGES + 255) / 256, 256>>>(dst);
    scan_kernel<<<1, 1024>>>();
    fill_kernel<<<(N_EDGES + 255) / 256, 256>>>(src, dst);

    // input fc
    input_kernel<<<(N_NODES * 64 + 255) / 256, 256>>>(x, Win);

    dim3 ggrid(391, 4);
    for (int l = 0; l < LAYERS; l++) {
        agg_kernel<<<(N_NODES * 32 + 255) / 256, 256>>>();
        sgemm_kernel<<<ggrid, 256>>>(p_agg, Wrel + l * HID * HID,
                                     p_h, Wroot + l * HID * HID,
                                     brel + l * HID, p_out, HID);
        zstats_kernel<<<1, 256>>>();
        stats_kernel<<<200, 256>>>();
        bnfinal_kernel<<<1, 256>>>(gamma + l * HID, beta + l * HID);
        bnapply_kernel<<<(N_NODES * 64 + 255) / 256, 256>>>();
    }

    // per-node edge-MLP precompute: P = h@W1a^T + b1 ; Q = h@W1b^T
    sgemm_kernel<<<ggrid, 256>>>(p_h, W1, nullptr, nullptr, b1, p_P, 2 * HID);
    sgemm_kernel<<<ggrid, 256>>>(p_h, W1 + HID, nullptr, nullptr, nullptr, p_Q, 2 * HID);

    // fused edge MLP
    edge_kernel<<<(N_EDGES + ETM - 1) / ETM, 256, SMEM_EDGE>>>(src, dst, W2, b2, W3, b3, out);
}

// round 2
// speedup vs baseline: 1.7067x; 1.7067x over previous
#include <cuda_runtime.h>
#include <math.h>

#define N_NODES 50000
#define N_EDGES 500000
#define HID 256
#define LAYERS 15
#define EPS 1e-5f

// ---------------- device scratch (no allocs allowed) ----------------
__device__ float g_h[N_NODES * HID];
__device__ float g_agg[N_NODES * HID];
__device__ float g_out[N_NODES * HID];
__device__ float g_P[N_NODES * HID];
__device__ float g_Q[N_NODES * HID];
__device__ int   g_deg[N_NODES];
__device__ int   g_rowptr[N_NODES + 1];
__device__ int   g_cursor[N_NODES];
__device__ int   g_srcl[N_EDGES];
__device__ double g_sumd[HID];
__device__ double g_sqd[HID];
__device__ float g_scale[HID];
__device__ float g_shift[HID];

// ---------------- helpers ----------------
__device__ __forceinline__ unsigned f2tf32(float x) {
    unsigned r;
    asm("cvt.rna.tf32.f32 %0, %1;" : "=r"(r) : "f"(x));
    return r;
}
__device__ __forceinline__ void mma_tf32(float4& c,
    unsigned a0, unsigned a1, unsigned a2, unsigned a3,
    unsigned b0, unsigned b1)
{
    asm volatile(
        "mma.sync.aligned.m16n8k8.row.col.f32.tf32.tf32.f32 "
        "{%0,%1,%2,%3}, {%4,%5,%6,%7}, {%8,%9}, {%0,%1,%2,%3};"
        : "+f"(c.x), "+f"(c.y), "+f"(c.z), "+f"(c.w)
        : "r"(a0), "r"(a1), "r"(a2), "r"(a3), "r"(b0), "r"(b1));
}
__device__ __forceinline__ unsigned fbits(float x) { return __float_as_uint(x); }

// ---------------- CSR build ----------------
__global__ void zero_int_kernel() {
    int i = blockIdx.x * blockDim.x + threadIdx.x;
    if (i < N_NODES) { g_deg[i] = 0; g_cursor[i] = 0; }
}

__global__ void count_kernel(const int* __restrict__ dst) {
    int e = blockIdx.x * blockDim.x + threadIdx.x;
    if (e < N_EDGES) atomicAdd(&g_deg[dst[e]], 1);
}

__global__ void scan_kernel() {  // single block, 1024 threads
    __shared__ int s[1024];
    const int CH = (N_NODES + 1023) / 1024;
    int t = threadIdx.x;
    int start = t * CH;
    int end = start + CH; if (end > N_NODES) end = N_NODES;
    if (start > N_NODES) start = N_NODES;
    int sum = 0;
    for (int i = start; i < end; i++) sum += g_deg[i];
    s[t] = sum;
    __syncthreads();
    for (int off = 1; off < 1024; off <<= 1) {
        int v = 0;
        if (t >= off) v = s[t - off];
        __syncthreads();
        if (t >= off) s[t] += v;
        __syncthreads();
    }
    int run = (t == 0) ? 0 : s[t - 1];
    for (int i = start; i < end; i++) { g_rowptr[i] = run; run += g_deg[i]; }
    if (t == 1023) g_rowptr[N_NODES] = run;
}

__global__ void fill_kernel(const int* __restrict__ src, const int* __restrict__ dst) {
    int e = blockIdx.x * blockDim.x + threadIdx.x;
    if (e < N_EDGES) {
        int d = dst[e];
        int p = atomicAdd(&g_cursor[d], 1);
        g_srcl[g_rowptr[d] + p] = src[e];
    }
}

// ---------------- input fc: h = x @ W_in^T ----------------
__global__ void input_kernel(const float* __restrict__ x, const float* __restrict__ Win) {
    int idx = blockIdx.x * blockDim.x + threadIdx.x;
    if (idx >= N_NODES * 64) return;
    int node = idx >> 6;
    int c = (idx & 63) * 4;
    float x0 = x[node * 2 + 0];
    float x1 = x[node * 2 + 1];
    float4 o;
    o.x = x0 * Win[(c + 0) * 2] + x1 * Win[(c + 0) * 2 + 1];
    o.y = x0 * Win[(c + 1) * 2] + x1 * Win[(c + 1) * 2 + 1];
    o.z = x0 * Win[(c + 2) * 2] + x1 * Win[(c + 2) * 2 + 1];
    o.w = x0 * Win[(c + 3) * 2] + x1 * Win[(c + 3) * 2 + 1];
    ((float4*)g_h)[idx] = o;
}

// ---------------- aggregation: warp per node, CSR gather-sum ----------------
__global__ void agg_kernel() {
    int gt = blockIdx.x * blockDim.x + threadIdx.x;
    int node = gt >> 5;
    int lane = gt & 31;
    if (node >= N_NODES) return;
    int beg = g_rowptr[node], end = g_rowptr[node + 1];
    float4 a0 = make_float4(0.f, 0.f, 0.f, 0.f);
    float4 a1 = make_float4(0.f, 0.f, 0.f, 0.f);
    const float4* hp = (const float4*)g_h;
    for (int i = beg; i < end; i++) {
        int s = g_srcl[i];
        float4 x0 = hp[s * 64 + lane * 2];
        float4 x1 = hp[s * 64 + lane * 2 + 1];
        a0.x += x0.x; a0.y += x0.y; a0.z += x0.z; a0.w += x0.w;
        a1.x += x1.x; a1.y += x1.y; a1.z += x1.z; a1.w += x1.w;
    }
    ((float4*)g_agg)[node * 64 + lane * 2] = a0;
    ((float4*)g_agg)[node * 64 + lane * 2 + 1] = a1;
}

// ---------------- tensor-core GEMM: C[M,256] = A1@W1^T (+ A2@W2^T) (+ bias) ----------------
// BM=128, BN=128, BK=32. 8 warps: 2 (m) x 4 (n). Warp tile 64x32.
// As[k][m] stride 136 (136%32==8 -> conflict-free frag loads)
// Bs[k][n] stride 136
#define AS_S 136
__global__ void __launch_bounds__(256) tc_gemm_kernel(
    const float* __restrict__ A1, const float* __restrict__ W1,
    const float* __restrict__ A2, const float* __restrict__ W2,
    const float* __restrict__ bias, float* __restrict__ C, int ldw)
{
    __shared__ float As[32 * AS_S];
    __shared__ float Bs[32 * AS_S];
    int tid = threadIdx.x;
    int lane = tid & 31, wid = tid >> 5;
    int warp_m = wid >> 2;          // 0..1 -> 64 rows
    int warp_n = wid & 3;           // 0..3 -> 32 cols
    int tg = lane & 3;              // thread-in-group (k)
    int gid = lane >> 2;            // group id (0..7)
    int bm = blockIdx.x, bn = blockIdx.y;
    int rowC0 = bm * 128;

    float4 acc[4][4];
#pragma unroll
    for (int i = 0; i < 4; i++)
#pragma unroll
        for (int j = 0; j < 4; j++) acc[i][j] = make_float4(0.f, 0.f, 0.f, 0.f);

    for (int pass = 0; pass < 2; pass++) {
        const float* A = pass ? A2 : A1;
        const float* W = pass ? W2 : W1;
        if (!A) break;
        for (int kc = 0; kc < HID; kc += 32) {
            // stage A tile [128 m][32 k] -> As[k][m] (tf32-rounded)
#pragma unroll
            for (int it = 0; it < 4; it++) {
                int idx = it * 256 + tid;     // 0..1023 float4 units
                int m = idx >> 3;
                int k4 = (idx & 7) * 4;
                int row = rowC0 + m;
                float4 f = make_float4(0.f, 0.f, 0.f, 0.f);
                if (row < N_NODES) f = *(const float4*)&A[row * HID + kc + k4];
                As[(k4 + 0) * AS_S + m] = __uint_as_float(f2tf32(f.x));
                As[(k4 + 1) * AS_S + m] = __uint_as_float(f2tf32(f.y));
                As[(k4 + 2) * AS_S + m] = __uint_as_float(f2tf32(f.z));
                As[(k4 + 3) * AS_S + m] = __uint_as_float(f2tf32(f.w));
            }
            // stage W tile: Bs[k][n] = W[(bn*128+n)*ldw + kc+k]
#pragma unroll
            for (int it = 0; it < 4; it++) {
                int idx = it * 256 + tid;
                int n = idx >> 3;
                int k4 = (idx & 7) * 4;
                float4 f = *(const float4*)&W[(bn * 128 + n) * ldw + kc + k4];
                Bs[(k4 + 0) * AS_S + n] = __uint_as_float(f2tf32(f.x));
                Bs[(k4 + 1) * AS_S + n] = __uint_as_float(f2tf32(f.y));
                Bs[(k4 + 2) * AS_S + n] = __uint_as_float(f2tf32(f.z));
                Bs[(k4 + 3) * AS_S + n] = __uint_as_float(f2tf32(f.w));
            }
            __syncthreads();
#pragma unroll
            for (int kt = 0; kt < 4; kt++) {
                int k8 = kt * 8;
                unsigned a[4][4];
#pragma unroll
                for (int i = 0; i < 4; i++) {
                    int row = warp_m * 64 + i * 16 + gid;
                    a[i][0] = fbits(As[(k8 + tg) * AS_S + row]);
                    a[i][1] = fbits(As[(k8 + tg) * AS_S + row + 8]);
                    a[i][2] = fbits(As[(k8 + 4 + tg) * AS_S + row]);
                    a[i][3] = fbits(As[(k8 + 4 + tg) * AS_S + row + 8]);
                }
                unsigned b[4][2];
#pragma unroll
                for (int j = 0; j < 4; j++) {
                    int col = warp_n * 32 + j * 8 + gid;
                    b[j][0] = fbits(Bs[(k8 + tg) * AS_S + col]);
                    b[j][1] = fbits(Bs[(k8 + 4 + tg) * AS_S + col]);
                }
#pragma unroll
                for (int i = 0; i < 4; i++)
#pragma unroll
                    for (int j = 0; j < 4; j++)
                        mma_tf32(acc[i][j], a[i][0], a[i][1], a[i][2], a[i][3],
                                 b[j][0], b[j][1]);
            }
            __syncthreads();
        }
    }

    // epilogue
#pragma unroll
    for (int i = 0; i < 4; i++) {
#pragma unroll
        for (int j = 0; j < 4; j++) {
            int col = bn * 128 + warp_n * 32 + j * 8 + 2 * tg;
            float b0 = bias ? bias[col] : 0.f;
            float b1v = bias ? bias[col + 1] : 0.f;
            int row0 = rowC0 + warp_m * 64 + i * 16 + gid;
            if (row0 < N_NODES) {
                float2 o = make_float2(acc[i][j].x + b0, acc[i][j].y + b1v);
                *(float2*)&C[row0 * HID + col] = o;
            }
            int row1 = row0 + 8;
            if (row1 < N_NODES) {
                float2 o = make_float2(acc[i][j].z + b0, acc[i][j].w + b1v);
                *(float2*)&C[row1 * HID + col] = o;
            }
        }
    }
}

// ---------------- BN stats ----------------
__global__ void zstats_kernel() {
    int c = threadIdx.x;
    g_sumd[c] = 0.0; g_sqd[c] = 0.0;
}

__global__ void stats_kernel() {
    int c = threadIdx.x;
    int r0 = blockIdx.x * 250;
    int r1 = r0 + 250; if (r1 > N_NODES) r1 = N_NODES;
    float s = 0.f, q = 0.f;
    for (int r = r0; r < r1; r++) {
        float v = g_out[r * HID + c];
        s += v; q += v * v;
    }
    atomicAdd(&g_sumd[c], (double)s);
    atomicAdd(&g_sqd[c], (double)q);
}

__global__ void bnfinal_kernel(const float* __restrict__ gamma, const float* __restrict__ beta) {
    int c = threadIdx.x;
    float mean = (float)(g_sumd[c] / (double)N_NODES);
    float var = (float)(g_sqd[c] / (double)N_NODES) - mean * mean;
    float rstd = rsqrtf(var + EPS);
    float sc = rstd * gamma[c];
    g_scale[c] = sc;
    g_shift[c] = beta[c] - mean * sc;
}

__global__ void bnapply_kernel() {
    int idx = blockIdx.x * blockDim.x + threadIdx.x;
    if (idx >= N_NODES * 64) return;
    int c4 = idx & 63;
    float4 o = ((const float4*)g_out)[idx];
    float4 h = ((float4*)g_h)[idx];
    float4 sc = ((const float4*)g_scale)[c4];
    float4 sh = ((const float4*)g_shift)[c4];
    h.x += fmaxf(o.x * sc.x + sh.x, 0.f);
    h.y += fmaxf(o.y * sc.y + sh.y, 0.f);
    h.z += fmaxf(o.z * sc.z + sh.z, 0.f);
    h.w += fmaxf(o.w * sc.w + sh.w, 0.f);
    ((float4*)g_h)[idx] = h;
}

// ---------------- fused edge MLP (tensor cores) ----------------
// z1 = relu(P[src] + Q[dst])   (b1 folded into P), tf32-rounded in smem
// z2 = relu(z1 @ W2^T + b2) ; out = sigmoid(z2 @ W3^T + b3)
// ETM=128 edges/block. 8 warps: 4 (m) x 2 (n). Warp tile 32 x 128.
#define ETM 128
#define Z1S 260     // 260 % 32 == 4 -> conflict-free A-frag loads (row-major)
#define BSS 264     // 264 % 32 == 8 -> conflict-free B-frag loads (k-major)
#define EDGE_SMEM ((ETM * Z1S + 32 * BSS + 2 * ETM) * 4 + 2 * ETM * 4)

__global__ void __launch_bounds__(256, 1) edge_kernel(
    const int* __restrict__ src, const int* __restrict__ dst,
    const float* __restrict__ W2, const float* __restrict__ b2,
    const float* __restrict__ W3, const float* __restrict__ b3,
    float* __restrict__ out)
{
    extern __shared__ float smem[];
    float* z1 = smem;                       // [ETM][Z1S]
    float* Bs = z1 + ETM * Z1S;             // [32][BSS]
    float* part = Bs + 32 * BSS;            // [2][ETM]
    int* se = (int*)(part + 2 * ETM);       // [ETM]
    int* de = se + ETM;                     // [ETM]

    int tid = threadIdx.x;
    int lane = tid & 31, wid = tid >> 5;
    int warp_m = wid >> 1;                  // 0..3 -> 32 rows
    int warp_n = wid & 1;                   // 0..1 -> 128 cols
    int tg = lane & 3;
    int gid = lane >> 2;
    int eb = blockIdx.x * ETM;

    if (tid < ETM) {
        int e = eb + tid;
        se[tid] = (e < N_EDGES) ? src[e] : 0;
        de[tid] = (e < N_EDGES) ? dst[e] : 0;
    }
    __syncthreads();

    // phase A: z1 tile = relu(P[s]+Q[d]), tf32 rounded
    const float4* Pp = (const float4*)g_P;
    const float4* Qp = (const float4*)g_Q;
#pragma unroll
    for (int it = 0; it < 32; it++) {
        int fid = it * 256 + tid;           // 0..8191 float4 units
        int i = fid >> 6;
        int c4 = fid & 63;
        float4 p = Pp[se[i] * 64 + c4];
        float4 q = Qp[de[i] * 64 + c4];
        float4 v;
        v.x = __uint_as_float(f2tf32(fmaxf(p.x + q.x, 0.f)));
        v.y = __uint_as_float(f2tf32(fmaxf(p.y + q.y, 0.f)));
        v.z = __uint_as_float(f2tf32(fmaxf(p.z + q.z, 0.f)));
        v.w = __uint_as_float(f2tf32(fmaxf(p.w + q.w, 0.f)));
        *(float4*)&z1[i * Z1S + c4 * 4] = v;
    }
    __syncthreads();

    // phase B: z2 = z1 @ W2^T via mma, acc[2 m-tiles][16 n-tiles]
    float4 acc[2][16];
#pragma unroll
    for (int i = 0; i < 2; i++)
#pragma unroll
        for (int j = 0; j < 16; j++) acc[i][j] = make_float4(0.f, 0.f, 0.f, 0.f);

    for (int kc = 0; kc < HID; kc += 32) {
        // stage Bs[k][n] = W2[n*256 + kc+k]  (n = 0..255)
        {
            int n = tid;
#pragma unroll
            for (int k4 = 0; k4 < 32; k4 += 4) {
                float4 f = *(const float4*)&W2[n * HID + kc + k4];
                Bs[(k4 + 0) * BSS + n] = __uint_as_float(f2tf32(f.x));
                Bs[(k4 + 1) * BSS + n] = __uint_as_float(f2tf32(f.y));
                Bs[(k4 + 2) * BSS + n] = __uint_as_float(f2tf32(f.z));
                Bs[(k4 + 3) * BSS + n] = __uint_as_float(f2tf32(f.w));
            }
        }
        __syncthreads();
#pragma unroll
        for (int kt = 0; kt < 4; kt++) {
            int k8 = kc + kt * 8;   // absolute k for z1, relative for Bs
            int k8r = kt * 8;
            unsigned a[2][4];
#pragma unroll
            for (int i = 0; i < 2; i++) {
                int row = warp_m * 32 + i * 16 + gid;
                a[i][0] = fbits(z1[row * Z1S + k8 + tg]);
                a[i][1] = fbits(z1[(row + 8) * Z1S + k8 + tg]);
                a[i][2] = fbits(z1[row * Z1S + k8 + 4 + tg]);
                a[i][3] = fbits(z1[(row + 8) * Z1S + k8 + 4 + tg]);
            }
#pragma unroll
            for (int j = 0; j < 16; j++) {
                int col = warp_n * 128 + j * 8 + gid;
                unsigned b0 = fbits(Bs[(k8r + tg) * BSS + col]);
                unsigned b1 = fbits(Bs[(k8r + 4 + tg) * BSS + col]);
#pragma unroll
                for (int i = 0; i < 2; i++)
                    mma_tf32(acc[i][j], a[i][0], a[i][1], a[i][2], a[i][3], b0, b1);
            }
        }
        __syncthreads();
    }

    // phase C: relu(z2+b2) . W3, reduce, sigmoid
    float res[2][2] = {{0.f, 0.f}, {0.f, 0.f}};   // [m-tile][row-half]
#pragma unroll
    for (int j = 0; j < 16; j++) {
        int col = warp_n * 128 + j * 8 + 2 * tg;
        float bb0 = b2[col],     w0 = W3[col];
        float bb1 = b2[col + 1], w1 = W3[col + 1];
#pragma unroll
        for (int i = 0; i < 2; i++) {
            res[i][0] += fmaxf(acc[i][j].x + bb0, 0.f) * w0
                       + fmaxf(acc[i][j].y + bb1, 0.f) * w1;
            res[i][1] += fmaxf(acc[i][j].z + bb0, 0.f) * w0
                       + fmaxf(acc[i][j].w + bb1, 0.f) * w1;
        }
    }
#pragma unroll
    for (int off = 1; off <= 2; off <<= 1) {
#pragma unroll
        for (int i = 0; i < 2; i++) {
            res[i][0] += __shfl_xor_sync(0xffffffffu, res[i][0], off);
            res[i][1] += __shfl_xor_sync(0xffffffffu, res[i][1], off);
        }
    }
    if (tg == 0) {
#pragma unroll
        for (int i = 0; i < 2; i++) {
            int row = warp_m * 32 + i * 16 + gid;
            part[warp_n * ETM + row] = res[i][0];
            part[warp_n * ETM + row + 8] = res[i][1];
        }
    }
    __syncthreads();
    if (tid < ETM) {
        int e = eb + tid;
        if (e < N_EDGES) {
            float v = part[tid] + part[ETM + tid] + b3[0];
            out[e] = 1.f / (1.f + expf(-v));
        }
    }
}

// ---------------- launcher ----------------
extern "C" void kernel_launch(void* const* d_in, const int* in_sizes, int n_in,
                              void* d_out, int out_size) {
    const float* x     = (const float*)d_in[0];
    const int*   ei    = (const int*)d_in[1];
    const float* Win   = (const float*)d_in[2];
    const float* Wrel  = (const float*)d_in[3];
    const float* brel  = (const float*)d_in[4];
    const float* Wroot = (const float*)d_in[5];
    const float* gamma = (const float*)d_in[6];
    const float* beta  = (const float*)d_in[7];
    const float* W1    = (const float*)d_in[8];
    const float* b1    = (const float*)d_in[9];
    const float* W2    = (const float*)d_in[10];
    const float* b2    = (const float*)d_in[11];
    const float* W3    = (const float*)d_in[12];
    const float* b3    = (const float*)d_in[13];
    float* out = (float*)d_out;
    const int* src = ei;
    const int* dst = ei + N_EDGES;

    float *p_agg, *p_h, *p_out, *p_P, *p_Q;
    cudaGetSymbolAddress((void**)&p_agg, g_agg);
    cudaGetSymbolAddress((void**)&p_h, g_h);
    cudaGetSymbolAddress((void**)&p_out, g_out);
    cudaGetSymbolAddress((void**)&p_P, g_P);
    cudaGetSymbolAddress((void**)&p_Q, g_Q);

    cudaFuncSetAttribute(edge_kernel, cudaFuncAttributeMaxDynamicSharedMemorySize, EDGE_SMEM);

    // CSR build
    zero_int_kernel<<<(N_NODES + 255) / 256, 256>>>();
    count_kernel<<<(N_EDGES + 255) / 256, 256>>>(dst);
    scan_kernel<<<1, 1024>>>();
    fill_kernel<<<(N_EDGES + 255) / 256, 256>>>(src, dst);

    // input fc
    input_kernel<<<(N_NODES * 64 + 255) / 256, 256>>>(x, Win);

    dim3 ggrid(391, 2);
    for (int l = 0; l < LAYERS; l++) {
        agg_kernel<<<(N_NODES * 32 + 255) / 256, 256>>>();
        tc_gemm_kernel<<<ggrid, 256>>>(p_agg, Wrel + l * HID * HID,
                                       p_h, Wroot + l * HID * HID,
                                       brel + l * HID, p_out, HID);
        zstats_kernel<<<1, 256>>>();
        stats_kernel<<<200, 256>>>();
        bnfinal_kernel<<<1, 256>>>(gamma + l * HID, beta + l * HID);
        bnapply_kernel<<<(N_NODES * 64 + 255) / 256, 256>>>();
    }

    // per-node edge-MLP precompute: P = h@W1a^T + b1 ; Q = h@W1b^T
    tc_gemm_kernel<<<ggrid, 256>>>(p_h, W1, nullptr, nullptr, b1, p_P, 2 * HID);
    tc_gemm_kernel<<<ggrid, 256>>>(p_h, W1 + HID, nullptr, nullptr, nullptr, p_Q, 2 * HID);

    // fused edge MLP
    edge_kernel<<<(N_EDGES + ETM - 1) / ETM, 256, EDGE_SMEM>>>(src, dst, W2, b2, W3, b3, out);
}

// round 3
// speedup vs baseline: 2.7004x; 1.5822x over previous
#include <cuda_runtime.h>
#include <cuda_bf16.h>
#include <math.h>

#define N_NODES 50000
#define N_EDGES 500000
#define HID 256
#define LAYERS 15
#define EPS 1e-5f

// ---------------- device scratch (no allocs allowed) ----------------
__device__ float    g_h[N_NODES * HID];          // fp32 residual stream
__device__ unsigned g_hbw[N_NODES * 128];        // bf16x2 shadow of h
__device__ unsigned g_aggbw[N_NODES * 128];      // bf16x2 aggregation
__device__ unsigned g_outbw[N_NODES * 128];      // bf16x2 layer output
__device__ unsigned g_Pbw[N_NODES * 128];        // bf16x2 P = h@W1a^T + b1
__device__ unsigned g_Qbw[N_NODES * 128];        // bf16x2 Q = h@W1b^T
__device__ int      g_deg[N_NODES];
__device__ int      g_rowptr[N_NODES + 1];
__device__ int      g_cursor[N_NODES];
__device__ int      g_srcl[N_EDGES];
__device__ double   g_sumd[HID];
__device__ double   g_sqd[HID];
__device__ float    g_scale[HID];
__device__ float    g_shift[HID];

// ---------------- helpers ----------------
__device__ __forceinline__ unsigned pack_bf2(float a, float b) {
    __nv_bfloat162 t = __floats2bfloat162_rn(a, b);
    return *reinterpret_cast<unsigned*>(&t);
}
__device__ __forceinline__ float2 unpack_bf2(unsigned u) {
    __nv_bfloat162 t = *reinterpret_cast<__nv_bfloat162*>(&u);
    return __bfloat1622float2(t);
}
__device__ __forceinline__ unsigned addrelu_bf2(unsigned p, unsigned q) {
    __nv_bfloat162 a = *reinterpret_cast<__nv_bfloat162*>(&p);
    __nv_bfloat162 b = *reinterpret_cast<__nv_bfloat162*>(&q);
    __nv_bfloat162 z = __float2bfloat162_rn(0.f);
    __nv_bfloat162 r = __hmax2(__hadd2(a, b), z);
    return *reinterpret_cast<unsigned*>(&r);
}
__device__ __forceinline__ void mma_bf16(float4& c,
    unsigned a0, unsigned a1, unsigned a2, unsigned a3,
    unsigned b0, unsigned b1)
{
    asm volatile(
        "mma.sync.aligned.m16n8k16.row.col.f32.bf16.bf16.f32 "
        "{%0,%1,%2,%3}, {%4,%5,%6,%7}, {%8,%9}, {%0,%1,%2,%3};"
        : "+f"(c.x), "+f"(c.y), "+f"(c.z), "+f"(c.w)
        : "r"(a0), "r"(a1), "r"(a2), "r"(a3), "r"(b0), "r"(b1));
}

// ---------------- CSR build ----------------
__global__ void zero_int_kernel() {
    int i = blockIdx.x * blockDim.x + threadIdx.x;
    if (i < N_NODES) { g_deg[i] = 0; g_cursor[i] = 0; }
}

__global__ void count_kernel(const int* __restrict__ dst) {
    int e = blockIdx.x * blockDim.x + threadIdx.x;
    if (e < N_EDGES) atomicAdd(&g_deg[dst[e]], 1);
}

__global__ void scan_kernel() {  // single block, 1024 threads
    __shared__ int s[1024];
    const int CH = (N_NODES + 1023) / 1024;
    int t = threadIdx.x;
    int start = t * CH;
    int end = start + CH; if (end > N_NODES) end = N_NODES;
    if (start > N_NODES) start = N_NODES;
    int sum = 0;
    for (int i = start; i < end; i++) sum += g_deg[i];
    s[t] = sum;
    __syncthreads();
    for (int off = 1; off < 1024; off <<= 1) {
        int v = 0;
        if (t >= off) v = s[t - off];
        __syncthreads();
        if (t >= off) s[t] += v;
        __syncthreads();
    }
    int run = (t == 0) ? 0 : s[t - 1];
    for (int i = start; i < end; i++) { g_rowptr[i] = run; run += g_deg[i]; }
    if (t == 1023) g_rowptr[N_NODES] = run;
}

__global__ void fill_kernel(const int* __restrict__ src, const int* __restrict__ dst) {
    int e = blockIdx.x * blockDim.x + threadIdx.x;
    if (e < N_EDGES) {
        int d = dst[e];
        int p = atomicAdd(&g_cursor[d], 1);
        g_srcl[g_rowptr[d] + p] = src[e];
    }
}

// ---------------- input fc: h = x @ W_in^T (fp32 h + bf16 shadow) ----------------
__global__ void input_kernel(const float* __restrict__ x, const float* __restrict__ Win) {
    int idx = blockIdx.x * blockDim.x + threadIdx.x;
    if (idx >= N_NODES * 64) return;
    int node = idx >> 6;
    int c = (idx & 63) * 4;
    float x0 = x[node * 2 + 0];
    float x1 = x[node * 2 + 1];
    float4 o;
    o.x = x0 * Win[(c + 0) * 2] + x1 * Win[(c + 0) * 2 + 1];
    o.y = x0 * Win[(c + 1) * 2] + x1 * Win[(c + 1) * 2 + 1];
    o.z = x0 * Win[(c + 2) * 2] + x1 * Win[(c + 2) * 2 + 1];
    o.w = x0 * Win[(c + 3) * 2] + x1 * Win[(c + 3) * 2 + 1];
    ((float4*)g_h)[idx] = o;
    g_hbw[idx * 2 + 0] = pack_bf2(o.x, o.y);
    g_hbw[idx * 2 + 1] = pack_bf2(o.z, o.w);
}

// ---------------- aggregation: warp per node, bf16 gather, fp32 sum ----------------
__global__ void agg_kernel() {
    int gt = blockIdx.x * blockDim.x + threadIdx.x;
    int node = gt >> 5;
    int lane = gt & 31;
    if (node >= N_NODES) return;
    int beg = g_rowptr[node], end = g_rowptr[node + 1];
    float2 a0 = make_float2(0.f, 0.f), a1 = a0, a2 = a0, a3 = a0;
    const uint4* hb = (const uint4*)g_hbw;   // 32 uint4 per node row
    for (int i = beg; i < end; i++) {
        int s = g_srcl[i];
        uint4 v = hb[s * 32 + lane];
        float2 f0 = unpack_bf2(v.x), f1 = unpack_bf2(v.y);
        float2 f2 = unpack_bf2(v.z), f3 = unpack_bf2(v.w);
        a0.x += f0.x; a0.y += f0.y; a1.x += f1.x; a1.y += f1.y;
        a2.x += f2.x; a2.y += f2.y; a3.x += f3.x; a3.y += f3.y;
    }
    uint4 o;
    o.x = pack_bf2(a0.x, a0.y); o.y = pack_bf2(a1.x, a1.y);
    o.z = pack_bf2(a2.x, a2.y); o.w = pack_bf2(a3.x, a3.y);
    ((uint4*)g_aggbw)[node * 32 + lane] = o;
}

// ---------------- bf16 tensor-core GEMM ----------------
// C[M,256](bf16) = A1@W1^T (+ A2@W2^T) (+ bias); optional fused BN column stats.
// BM=128 BN=128 BK=32. 8 warps 2(m)x4(n), warp tile 64x32, mma m16n8k16.
// Smem pair-layout: Xs2[k2][m] (k2 = k/2), stride 136 (136%32==8 -> conflict-free).
#define TS 136
__global__ void __launch_bounds__(256) tc_gemm_kernel(
    const unsigned* __restrict__ A1, const float* __restrict__ W1,
    const unsigned* __restrict__ A2, const float* __restrict__ W2,
    const float* __restrict__ bias, unsigned* __restrict__ Cb,
    int ldw, int dostats)
{
    __shared__ unsigned As2[16 * TS];
    __shared__ unsigned Bs2[16 * TS];
    int tid = threadIdx.x;
    int lane = tid & 31, wid = tid >> 5;
    int warp_m = wid >> 2;          // 0..1 -> 64 rows
    int warp_n = wid & 3;           // 0..3 -> 32 cols
    int tg = lane & 3;
    int gid = lane >> 2;
    int bm = blockIdx.x, bn = blockIdx.y;
    int rowC0 = bm * 128;

    float4 acc[4][4];
#pragma unroll
    for (int i = 0; i < 4; i++)
#pragma unroll
        for (int j = 0; j < 4; j++) acc[i][j] = make_float4(0.f, 0.f, 0.f, 0.f);

    for (int pass = 0; pass < 2; pass++) {
        const unsigned* A = pass ? A2 : A1;
        const float* W = pass ? W2 : W1;
        if (!A) break;
        for (int kc = 0; kc < HID; kc += 32) {
            int kc2 = kc >> 1;   // word offset
            // stage A tile: 128 m x 16 words -> As2[k2][m]
#pragma unroll
            for (int it = 0; it < 2; it++) {
                int idx = it * 256 + tid;     // 0..511 uint4 units
                int m = idx >> 2;
                int kq = (idx & 3) * 4;
                int row = rowC0 + m;
                uint4 v = make_uint4(0u, 0u, 0u, 0u);
                if (row < N_NODES) v = *(const uint4*)&A[row * 128 + kc2 + kq];
                As2[(kq + 0) * TS + m] = v.x;
                As2[(kq + 1) * TS + m] = v.y;
                As2[(kq + 2) * TS + m] = v.z;
                As2[(kq + 3) * TS + m] = v.w;
            }
            // stage W tile (fp32 -> bf16x2): Bs2[k2][n]
#pragma unroll
            for (int it = 0; it < 4; it++) {
                int idx = it * 256 + tid;     // 0..1023 float4 units
                int n = idx >> 3;
                int k4 = (idx & 7) * 4;
                float4 f = *(const float4*)&W[(bn * 128 + n) * ldw + kc + k4];
                Bs2[((k4 >> 1) + 0) * TS + n] = pack_bf2(f.x, f.y);
                Bs2[((k4 >> 1) + 1) * TS + n] = pack_bf2(f.z, f.w);
            }
            __syncthreads();
#pragma unroll
            for (int kt = 0; kt < 2; kt++) {
                int k2o = kt * 8;
                unsigned a[4][4];
#pragma unroll
                for (int i = 0; i < 4; i++) {
                    int row = warp_m * 64 + i * 16 + gid;
                    a[i][0] = As2[(k2o + tg) * TS + row];
                    a[i][1] = As2[(k2o + tg) * TS + row + 8];
                    a[i][2] = As2[(k2o + 4 + tg) * TS + row];
                    a[i][3] = As2[(k2o + 4 + tg) * TS + row + 8];
                }
                unsigned b[4][2];
#pragma unroll
                for (int j = 0; j < 4; j++) {
                    int col = warp_n * 32 + j * 8 + gid;
                    b[j][0] = Bs2[(k2o + tg) * TS + col];
                    b[j][1] = Bs2[(k2o + 4 + tg) * TS + col];
                }
#pragma unroll
                for (int i = 0; i < 4; i++)
#pragma unroll
                    for (int j = 0; j < 4; j++)
                        mma_bf16(acc[i][j], a[i][0], a[i][1], a[i][2], a[i][3],
                                 b[j][0], b[j][1]);
            }
            __syncthreads();
        }
    }

    // epilogue: bias, bf16 store, fused BN column stats
#pragma unroll
    for (int j = 0; j < 4; j++) {
        int col = bn * 128 + warp_n * 32 + j * 8 + 2 * tg;
        float b0 = bias ? bias[col] : 0.f;
        float b1v = bias ? bias[col + 1] : 0.f;
        float s0 = 0.f, s1 = 0.f, q0 = 0.f, q1 = 0.f;
#pragma unroll
        for (int i = 0; i < 4; i++) {
            int row0 = rowC0 + warp_m * 64 + i * 16 + gid;
            int row1 = row0 + 8;
            float ox = acc[i][j].x + b0, oy = acc[i][j].y + b1v;
            float oz = acc[i][j].z + b0, ow = acc[i][j].w + b1v;
            if (row0 < N_NODES) {
                Cb[row0 * 128 + (col >> 1)] = pack_bf2(ox, oy);
                s0 += ox; s1 += oy; q0 += ox * ox; q1 += oy * oy;
            }
            if (row1 < N_NODES) {
                Cb[row1 * 128 + (col >> 1)] = pack_bf2(oz, ow);
                s0 += oz; s1 += ow; q0 += oz * oz; q1 += ow * ow;
            }
        }
        if (dostats) {
#pragma unroll
            for (int off = 16; off >= 4; off >>= 1) {
                s0 += __shfl_down_sync(0xffffffffu, s0, off);
                s1 += __shfl_down_sync(0xffffffffu, s1, off);
                q0 += __shfl_down_sync(0xffffffffu, q0, off);
                q1 += __shfl_down_sync(0xffffffffu, q1, off);
            }
            if (lane < 4) {
                atomicAdd(&g_sumd[col], (double)s0);
                atomicAdd(&g_sumd[col + 1], (double)s1);
                atomicAdd(&g_sqd[col], (double)q0);
                atomicAdd(&g_sqd[col + 1], (double)q1);
            }
        }
    }
}

// ---------------- BN ----------------
__global__ void zstats_kernel() {
    int c = threadIdx.x;
    g_sumd[c] = 0.0; g_sqd[c] = 0.0;
}

__global__ void bnfinal_kernel(const float* __restrict__ gamma, const float* __restrict__ beta) {
    int c = threadIdx.x;
    float mean = (float)(g_sumd[c] / (double)N_NODES);
    float var = (float)(g_sqd[c] / (double)N_NODES) - mean * mean;
    float rstd = rsqrtf(var + EPS);
    float sc = rstd * gamma[c];
    g_scale[c] = sc;
    g_shift[c] = beta[c] - mean * sc;
}

__global__ void bnapply_kernel() {
    int idx = blockIdx.x * blockDim.x + threadIdx.x;  // float4 units of h
    if (idx >= N_NODES * 64) return;
    int c4 = idx & 63;
    float2 o01 = unpack_bf2(g_outbw[idx * 2 + 0]);
    float2 o23 = unpack_bf2(g_outbw[idx * 2 + 1]);
    float4 h = ((float4*)g_h)[idx];
    float4 sc = ((const float4*)g_scale)[c4];
    float4 sh = ((const float4*)g_shift)[c4];
    h.x += fmaxf(o01.x * sc.x + sh.x, 0.f);
    h.y += fmaxf(o01.y * sc.y + sh.y, 0.f);
    h.z += fmaxf(o23.x * sc.z + sh.z, 0.f);
    h.w += fmaxf(o23.y * sc.w + sh.w, 0.f);
    ((float4*)g_h)[idx] = h;
    g_hbw[idx * 2 + 0] = pack_bf2(h.x, h.y);
    g_hbw[idx * 2 + 1] = pack_bf2(h.z, h.w);
}

// ---------------- fused edge MLP (bf16 tensor cores) ----------------
// z1 = relu(P[src]+Q[dst]) in bf16; z2 = relu(z1@W2^T + b2); out = sigmoid(z2@W3^T + b3)
// ETM=128 edges/block. 8 warps: 4(m) x 2(n). Warp tile 32x128.
#define ETM 128
#define Z1S 132     // word stride, 132%32==4 -> conflict-free A-frag loads
#define BSS 264     // word stride, 264%32==8 -> conflict-free B-frag loads
#define EDGE_SMEM ((ETM * Z1S + 16 * BSS) * 4 + 2 * ETM * 4 + 2 * ETM * 4)

__global__ void __launch_bounds__(256, 1) edge_kernel(
    const int* __restrict__ src, const int* __restrict__ dst,
    const float* __restrict__ W2, const float* __restrict__ b2,
    const float* __restrict__ W3, const float* __restrict__ b3,
    float* __restrict__ out)
{
    extern __shared__ unsigned smem[];
    unsigned* z12 = smem;                   // [ETM][Z1S] bf16x2 words
    unsigned* Bs2 = z12 + ETM * Z1S;        // [16][BSS]
    float* part = (float*)(Bs2 + 16 * BSS); // [2][ETM]
    int* se = (int*)(part + 2 * ETM);       // [ETM]
    int* de = se + ETM;                     // [ETM]

    int tid = threadIdx.x;
    int lane = tid & 31, wid = tid >> 5;
    int warp_m = wid >> 1;                  // 0..3 -> 32 rows
    int warp_n = wid & 1;                   // 0..1 -> 128 cols
    int tg = lane & 3;
    int gid = lane >> 2;
    int eb = blockIdx.x * ETM;

    if (tid < ETM) {
        int e = eb + tid;
        se[tid] = (e < N_EDGES) ? src[e] : 0;
        de[tid] = (e < N_EDGES) ? dst[e] : 0;
    }
    __syncthreads();

    // phase A: z1 tile = relu(P[s]+Q[d]) in bf16x2 words
#pragma unroll
    for (int it = 0; it < 64; it++) {
        int fid = it * 256 + tid;           // 0..16383 words
        int i = fid >> 7;
        int w = fid & 127;
        unsigned p = g_Pbw[se[i] * 128 + w];
        unsigned q = g_Qbw[de[i] * 128 + w];
        z12[i * Z1S + w] = addrelu_bf2(p, q);
    }
    __syncthreads();

    // phase B: z2 = z1 @ W2^T
    float4 acc[2][16];
#pragma unroll
    for (int i = 0; i < 2; i++)
#pragma unroll
        for (int j = 0; j < 16; j++) acc[i][j] = make_float4(0.f, 0.f, 0.f, 0.f);

    for (int kc = 0; kc < HID; kc += 32) {
        // stage W2 chunk: Bs2[k2][n], n = 0..255
        {
            int n = tid;
#pragma unroll
            for (int k4 = 0; k4 < 32; k4 += 4) {
                float4 f = *(const float4*)&W2[n * HID + kc + k4];
                Bs2[((k4 >> 1) + 0) * BSS + n] = pack_bf2(f.x, f.y);
                Bs2[((k4 >> 1) + 1) * BSS + n] = pack_bf2(f.z, f.w);
            }
        }
        __syncthreads();
#pragma unroll
        for (int kt = 0; kt < 2; kt++) {
            int k2a = (kc >> 1) + kt * 8;   // absolute word-k for z12
            int k2o = kt * 8;               // relative for Bs2
            unsigned a[2][4];
#pragma unroll
            for (int i = 0; i < 2; i++) {
                int row = warp_m * 32 + i * 16 + gid;
                a[i][0] = z12[row * Z1S + k2a + tg];
                a[i][1] = z12[(row + 8) * Z1S + k2a + tg];
                a[i][2] = z12[row * Z1S + k2a + 4 + tg];
                a[i][3] = z12[(row + 8) * Z1S + k2a + 4 + tg];
            }
#pragma unroll
            for (int j = 0; j < 16; j++) {
                int col = warp_n * 128 + j * 8 + gid;
                unsigned b0 = Bs2[(k2o + tg) * BSS + col];
                unsigned b1 = Bs2[(k2o + 4 + tg) * BSS + col];
#pragma unroll
                for (int i = 0; i < 2; i++)
                    mma_bf16(acc[i][j], a[i][0], a[i][1], a[i][2], a[i][3], b0, b1);
            }
        }
        __syncthreads();
    }

    // phase C: relu(z2+b2) . W3, reduce, sigmoid
    float res[2][2] = {{0.f, 0.f}, {0.f, 0.f}};
#pragma unroll
    for (int j = 0; j < 16; j++) {
        int col = warp_n * 128 + j * 8 + 2 * tg;
        float bb0 = b2[col],     w0 = W3[col];
        float bb1 = b2[col + 1], w1 = W3[col + 1];
#pragma unroll
        for (int i = 0; i < 2; i++) {
            res[i][0] += fmaxf(acc[i][j].x + bb0, 0.f) * w0
                       + fmaxf(acc[i][j].y + bb1, 0.f) * w1;
            res[i][1] += fmaxf(acc[i][j].z + bb0, 0.f) * w0
                       + fmaxf(acc[i][j].w + bb1, 0.f) * w1;
        }
    }
#pragma unroll
    for (int off = 1; off <= 2; off <<= 1) {
#pragma unroll
        for (int i = 0; i < 2; i++) {
            res[i][0] += __shfl_xor_sync(0xffffffffu, res[i][0], off);
            res[i][1] += __shfl_xor_sync(0xffffffffu, res[i][1], off);
        }
    }
    if (tg == 0) {
#pragma unroll
        for (int i = 0; i < 2; i++) {
            int row = warp_m * 32 + i * 16 + gid;
            part[warp_n * ETM + row] = res[i][0];
            part[warp_n * ETM + row + 8] = res[i][1];
        }
    }
    __syncthreads();
    if (tid < ETM) {
        int e = eb + tid;
        if (e < N_EDGES) {
            float v = part[tid] + part[ETM + tid] + b3[0];
            out[e] = 1.f / (1.f + expf(-v));
        }
    }
}

// ---------------- launcher ----------------
extern "C" void kernel_launch(void* const* d_in, const int* in_sizes, int n_in,
                              void* d_out, int out_size) {
    const float* x     = (const float*)d_in[0];
    const int*   ei    = (const int*)d_in[1];
    const float* Win   = (const float*)d_in[2];
    const float* Wrel  = (const float*)d_in[3];
    const float* brel  = (const float*)d_in[4];
    const float* Wroot = (const float*)d_in[5];
    const float* gamma = (const float*)d_in[6];
    const float* beta  = (const float*)d_in[7];
    const float* W1    = (const float*)d_in[8];
    const float* b1    = (const float*)d_in[9];
    const float* W2    = (const float*)d_in[10];
    const float* b2    = (const float*)d_in[11];
    const float* W3    = (const float*)d_in[12];
    const float* b3    = (const float*)d_in[13];
    float* out = (float*)d_out;
    const int* src = ei;
    const int* dst = ei + N_EDGES;

    unsigned *p_aggb, *p_hb, *p_outb, *p_Pb, *p_Qb;
    cudaGetSymbolAddress((void**)&p_aggb, g_aggbw);
    cudaGetSymbolAddress((void**)&p_hb, g_hbw);
    cudaGetSymbolAddress((void**)&p_outb, g_outbw);
    cudaGetSymbolAddress((void**)&p_Pb, g_Pbw);
    cudaGetSymbolAddress((void**)&p_Qb, g_Qbw);

    cudaFuncSetAttribute(edge_kernel, cudaFuncAttributeMaxDynamicSharedMemorySize, EDGE_SMEM);

    // CSR build
    zero_int_kernel<<<(N_NODES + 255) / 256, 256>>>();
    count_kernel<<<(N_EDGES + 255) / 256, 256>>>(dst);
    scan_kernel<<<1, 1024>>>();
    fill_kernel<<<(N_EDGES + 255) / 256, 256>>>(src, dst);

    // input fc
    input_kernel<<<(N_NODES * 64 + 255) / 256, 256>>>(x, Win);

    dim3 ggrid(391, 2);
    for (int l = 0; l < LAYERS; l++) {
        agg_kernel<<<(N_NODES * 32 + 255) / 256, 256>>>();
        zstats_kernel<<<1, 256>>>();
        tc_gemm_kernel<<<ggrid, 256>>>(p_aggb, Wrel + l * HID * HID,
                                       p_hb, Wroot + l * HID * HID,
                                       brel + l * HID, p_outb, HID, 1);
        bnfinal_kernel<<<1, 256>>>(gamma + l * HID, beta + l * HID);
        bnapply_kernel<<<(N_NODES * 64 + 255) / 256, 256>>>();
    }

    // per-node edge-MLP precompute: P = h@W1a^T + b1 ; Q = h@W1b^T  (bf16 out)
    tc_gemm_kernel<<<ggrid, 256>>>(p_hb, W1, nullptr, nullptr, b1, p_Pb, 2 * HID, 0);
    tc_gemm_kernel<<<ggrid, 256>>>(p_hb, W1 + HID, nullptr, nullptr, nullptr, p_Qb, 2 * HID, 0);

    // fused edge MLP
    edge_kernel<<<(N_EDGES + ETM - 1) / ETM, 256, EDGE_SMEM>>>(src, dst, W2, b2, W3, b3, out);
}

// round 4
// speedup vs baseline: 3.3835x; 1.2529x over previous
#include <cuda_runtime.h>
#include <cuda_bf16.h>
#include <math.h>

#define N_NODES 50000
#define N_EDGES 500000
#define HID 256
#define LAYERS 15
#define EPS 1e-5f

// packed bf16 weight buffer offsets (in 32-bit words)
#define WOFF_REL  0
#define WOFF_ROOT 491520
#define WOFF_W1A  983040
#define WOFF_W1B  1015808
#define WOFF_W2   1048576
#define WB_TOTAL  1081344

// ---------------- device scratch (no allocs allowed) ----------------
__device__ float    g_h[N_NODES * HID];          // fp32 residual stream
__device__ unsigned g_hbw[N_NODES * 128];        // bf16x2 shadow of h
__device__ unsigned g_aggbw[N_NODES * 128];      // bf16x2 aggregation
__device__ unsigned g_outbw[N_NODES * 128];      // bf16x2 layer output
__device__ unsigned g_Pbw[N_NODES * 128];        // bf16x2 P = h@W1a^T + b1
__device__ unsigned g_Qbw[N_NODES * 128];        // bf16x2 Q = h@W1b^T
__device__ unsigned g_Wb[WB_TOTAL];              // all weights, bf16x2
__device__ int      g_deg[N_NODES];
__device__ int      g_rowptr[N_NODES + 1];
__device__ int      g_cursor[N_NODES];
__device__ int      g_srcl[N_EDGES];
__device__ double   g_sumd[HID];
__device__ double   g_sqd[HID];
__device__ float    g_scale[HID];
__device__ float    g_shift[HID];

// ---------------- helpers ----------------
__device__ __forceinline__ unsigned pack_bf2(float a, float b) {
    __nv_bfloat162 t = __floats2bfloat162_rn(a, b);
    return *reinterpret_cast<unsigned*>(&t);
}
__device__ __forceinline__ float2 unpack_bf2(unsigned u) {
    __nv_bfloat162 t = *reinterpret_cast<__nv_bfloat162*>(&u);
    return __bfloat1622float2(t);
}
__device__ __forceinline__ unsigned addrelu_bf2(unsigned p, unsigned q) {
    __nv_bfloat162 a = *reinterpret_cast<__nv_bfloat162*>(&p);
    __nv_bfloat162 b = *reinterpret_cast<__nv_bfloat162*>(&q);
    __nv_bfloat162 z = __float2bfloat162_rn(0.f);
    __nv_bfloat162 r = __hmax2(__hadd2(a, b), z);
    return *reinterpret_cast<unsigned*>(&r);
}
__device__ __forceinline__ void mma_bf16(float4& c,
    unsigned a0, unsigned a1, unsigned a2, unsigned a3,
    unsigned b0, unsigned b1)
{
    asm volatile(
        "mma.sync.aligned.m16n8k16.row.col.f32.bf16.bf16.f32 "
        "{%0,%1,%2,%3}, {%4,%5,%6,%7}, {%8,%9}, {%0,%1,%2,%3};"
        : "+f"(c.x), "+f"(c.y), "+f"(c.z), "+f"(c.w)
        : "r"(a0), "r"(a1), "r"(a2), "r"(a3), "r"(b0), "r"(b1));
}

// ---------------- weight conversion: fp32 [n][ld] (+coloff) -> bf16x2 words ----------------
__global__ void convw_kernel(const float* __restrict__ src, unsigned* __restrict__ dst,
                             int ld, int coloff, int nwords) {
    int idx = blockIdx.x * blockDim.x + threadIdx.x;
    if (idx >= nwords) return;
    int n = idx >> 7;          // 128 words per 256-col row
    int k2 = idx & 127;
    const float* s = src + n * ld + coloff + 2 * k2;
    dst[idx] = pack_bf2(s[0], s[1]);
}

// ---------------- CSR build ----------------
__global__ void zero_int_kernel() {
    int i = blockIdx.x * blockDim.x + threadIdx.x;
    if (i < N_NODES) { g_deg[i] = 0; g_cursor[i] = 0; }
    if (i < HID) { g_sumd[i] = 0.0; g_sqd[i] = 0.0; }
}

__global__ void count_kernel(const int* __restrict__ dst) {
    int e = blockIdx.x * blockDim.x + threadIdx.x;
    if (e < N_EDGES) atomicAdd(&g_deg[dst[e]], 1);
}

__global__ void scan_kernel() {  // single block, 1024 threads
    __shared__ int s[1024];
    const int CH = (N_NODES + 1023) / 1024;
    int t = threadIdx.x;
    int start = t * CH;
    int end = start + CH; if (end > N_NODES) end = N_NODES;
    if (start > N_NODES) start = N_NODES;
    int sum = 0;
    for (int i = start; i < end; i++) sum += g_deg[i];
    s[t] = sum;
    __syncthreads();
    for (int off = 1; off < 1024; off <<= 1) {
        int v = 0;
        if (t >= off) v = s[t - off];
        __syncthreads();
        if (t >= off) s[t] += v;
        __syncthreads();
    }
    int run = (t == 0) ? 0 : s[t - 1];
    for (int i = start; i < end; i++) { g_rowptr[i] = run; run += g_deg[i]; }
    if (t == 1023) g_rowptr[N_NODES] = run;
}

__global__ void fill_kernel(const int* __restrict__ src, const int* __restrict__ dst) {
    int e = blockIdx.x * blockDim.x + threadIdx.x;
    if (e < N_EDGES) {
        int d = dst[e];
        int p = atomicAdd(&g_cursor[d], 1);
        g_srcl[g_rowptr[d] + p] = src[e];
    }
}

// ---------------- input fc ----------------
__global__ void input_kernel(const float* __restrict__ x, const float* __restrict__ Win) {
    int idx = blockIdx.x * blockDim.x + threadIdx.x;
    if (idx >= N_NODES * 64) return;
    int node = idx >> 6;
    int c = (idx & 63) * 4;
    float x0 = x[node * 2 + 0];
    float x1 = x[node * 2 + 1];
    float4 o;
    o.x = x0 * Win[(c + 0) * 2] + x1 * Win[(c + 0) * 2 + 1];
    o.y = x0 * Win[(c + 1) * 2] + x1 * Win[(c + 1) * 2 + 1];
    o.z = x0 * Win[(c + 2) * 2] + x1 * Win[(c + 2) * 2 + 1];
    o.w = x0 * Win[(c + 3) * 2] + x1 * Win[(c + 3) * 2 + 1];
    ((float4*)g_h)[idx] = o;
    g_hbw[idx * 2 + 0] = pack_bf2(o.x, o.y);
    g_hbw[idx * 2 + 1] = pack_bf2(o.z, o.w);
}

// ---------------- aggregation ----------------
__global__ void agg_kernel() {
    int gt = blockIdx.x * blockDim.x + threadIdx.x;
    int node = gt >> 5;
    int lane = gt & 31;
    if (node >= N_NODES) return;
    int beg = g_rowptr[node], end = g_rowptr[node + 1];
    float2 a0 = make_float2(0.f, 0.f), a1 = a0, a2 = a0, a3 = a0;
    const uint4* hb = (const uint4*)g_hbw;
    for (int i = beg; i < end; i++) {
        int s = g_srcl[i];
        uint4 v = hb[s * 32 + lane];
        float2 f0 = unpack_bf2(v.x), f1 = unpack_bf2(v.y);
        float2 f2 = unpack_bf2(v.z), f3 = unpack_bf2(v.w);
        a0.x += f0.x; a0.y += f0.y; a1.x += f1.x; a1.y += f1.y;
        a2.x += f2.x; a2.y += f2.y; a3.x += f3.x; a3.y += f3.y;
    }
    uint4 o;
    o.x = pack_bf2(a0.x, a0.y); o.y = pack_bf2(a1.x, a1.y);
    o.z = pack_bf2(a2.x, a2.y); o.w = pack_bf2(a3.x, a3.y);
    ((uint4*)g_aggbw)[node * 32 + lane] = o;
}

// ---------------- bf16 TC GEMM, double-buffered, all-bf16 staging ----------------
// C = A1@B1^T (+ A2@B2^T) (+ bias). A,B bf16x2 word arrays, row stride 128 words.
// BM=128 BN=128 BK=32. 8 warps 2x4, warp tile 64x32. Row-major smem tiles, stride 36.
#define GTS 36
#define GEMM_SMEM (4 * 128 * GTS * 4)   // 2 bufs x (A+B) = 73728 B
__global__ void __launch_bounds__(256) tc_gemm_kernel(
    const unsigned* __restrict__ A1, const unsigned* __restrict__ B1,
    const unsigned* __restrict__ A2, const unsigned* __restrict__ B2,
    const float* __restrict__ bias, unsigned* __restrict__ Cb,
    int dostats, int npass)
{
    extern __shared__ unsigned gsm[];
    int tid = threadIdx.x;
    int lane = tid & 31, wid = tid >> 5;
    int warp_m = wid >> 2, warp_n = wid & 3;
    int tg = lane & 3, gid = lane >> 2;
    int bm = blockIdx.x, bn = blockIdx.y;
    int rowC0 = bm * 128;
    int nchunks = npass * 8;
    int sm_i = tid >> 2;           // 0..63 (+64 per it)
    int sq = (tid & 3) * 4;        // word quad offset

    float4 acc[4][4];
#pragma unroll
    for (int i = 0; i < 4; i++)
#pragma unroll
        for (int j = 0; j < 4; j++) acc[i][j] = make_float4(0.f, 0.f, 0.f, 0.f);

    uint4 aR[2], bR[2];

    auto loadc = [&](int c) {
        const unsigned* A = (c < 8) ? A1 : A2;
        const unsigned* B = (c < 8) ? B1 : B2;
        int kc2 = (c & 7) * 16;
#pragma unroll
        for (int it = 0; it < 2; it++) {
            int m = sm_i + it * 64;
            int row = rowC0 + m;
            aR[it] = (row < N_NODES) ? *(const uint4*)&A[row * 128 + kc2 + sq]
                                     : make_uint4(0u, 0u, 0u, 0u);
            bR[it] = *(const uint4*)&B[(bn * 128 + m) * 128 + kc2 + sq];
        }
    };
    auto storec = [&](int buf) {
        unsigned* As = gsm + buf * (128 * GTS);
        unsigned* Bs = gsm + 2 * (128 * GTS) + buf * (128 * GTS);
#pragma unroll
        for (int it = 0; it < 2; it++) {
            int m = sm_i + it * 64;
            *(uint4*)&As[m * GTS + sq] = aR[it];
            *(uint4*)&Bs[m * GTS + sq] = bR[it];
        }
    };
    auto compute = [&](int buf) {
        const unsigned* As = gsm + buf * (128 * GTS);
        const unsigned* Bs = gsm + 2 * (128 * GTS) + buf * (128 * GTS);
#pragma unroll
        for (int kt = 0; kt < 2; kt++) {
            int k2o = kt * 8;
            unsigned a[4][4];
#pragma unroll
            for (int i = 0; i < 4; i++) {
                int row = warp_m * 64 + i * 16 + gid;
                a[i][0] = As[row * GTS + k2o + tg];
                a[i][1] = As[(row + 8) * GTS + k2o + tg];
                a[i][2] = As[row * GTS + k2o + 4 + tg];
                a[i][3] = As[(row + 8) * GTS + k2o + 4 + tg];
            }
            unsigned b[4][2];
#pragma unroll
            for (int j = 0; j < 4; j++) {
                int col = warp_n * 32 + j * 8 + gid;
                b[j][0] = Bs[col * GTS + k2o + tg];
                b[j][1] = Bs[col * GTS + k2o + 4 + tg];
            }
#pragma unroll
            for (int i = 0; i < 4; i++)
#pragma unroll
                for (int j = 0; j < 4; j++)
                    mma_bf16(acc[i][j], a[i][0], a[i][1], a[i][2], a[i][3],
                             b[j][0], b[j][1]);
        }
    };

    loadc(0); storec(0); __syncthreads();
    for (int c = 0; c < nchunks; c++) {
        if (c + 1 < nchunks) loadc(c + 1);
        compute(c & 1);
        if (c + 1 < nchunks) storec((c + 1) & 1);
        __syncthreads();
    }

    // epilogue: bias, bf16 store, fused BN stats
#pragma unroll
    for (int j = 0; j < 4; j++) {
        int col = bn * 128 + warp_n * 32 + j * 8 + 2 * tg;
        float b0 = bias ? bias[col] : 0.f;
        float b1v = bias ? bias[col + 1] : 0.f;
        float s0 = 0.f, s1 = 0.f, q0 = 0.f, q1 = 0.f;
#pragma unroll
        for (int i = 0; i < 4; i++) {
            int row0 = rowC0 + warp_m * 64 + i * 16 + gid;
            int row1 = row0 + 8;
            float ox = acc[i][j].x + b0, oy = acc[i][j].y + b1v;
            float oz = acc[i][j].z + b0, ow = acc[i][j].w + b1v;
            if (row0 < N_NODES) {
                Cb[row0 * 128 + (col >> 1)] = pack_bf2(ox, oy);
                s0 += ox; s1 += oy; q0 += ox * ox; q1 += oy * oy;
            }
            if (row1 < N_NODES) {
                Cb[row1 * 128 + (col >> 1)] = pack_bf2(oz, ow);
                s0 += oz; s1 += ow; q0 += oz * oz; q1 += ow * ow;
            }
        }
        if (dostats) {
#pragma unroll
            for (int off = 16; off >= 4; off >>= 1) {
                s0 += __shfl_down_sync(0xffffffffu, s0, off);
                s1 += __shfl_down_sync(0xffffffffu, s1, off);
                q0 += __shfl_down_sync(0xffffffffu, q0, off);
                q1 += __shfl_down_sync(0xffffffffu, q1, off);
            }
            if (lane < 4) {
                atomicAdd(&g_sumd[col], (double)s0);
                atomicAdd(&g_sumd[col + 1], (double)s1);
                atomicAdd(&g_sqd[col], (double)q0);
                atomicAdd(&g_sqd[col + 1], (double)q1);
            }
        }
    }
}

// ---------------- BN ----------------
__global__ void bnfinal_kernel(const float* __restrict__ gamma, const float* __restrict__ beta) {
    int c = threadIdx.x;
    double sd = g_sumd[c], sq = g_sqd[c];
    g_sumd[c] = 0.0; g_sqd[c] = 0.0;   // ready for next layer
    float mean = (float)(sd / (double)N_NODES);
    float var = (float)(sq / (double)N_NODES) - mean * mean;
    float rstd = rsqrtf(var + EPS);
    float sc = rstd * gamma[c];
    g_scale[c] = sc;
    g_shift[c] = beta[c] - mean * sc;
}

__global__ void bnapply_kernel() {
    int idx = blockIdx.x * blockDim.x + threadIdx.x;
    if (idx >= N_NODES * 64) return;
    int c4 = idx & 63;
    float2 o01 = unpack_bf2(g_outbw[idx * 2 + 0]);
    float2 o23 = unpack_bf2(g_outbw[idx * 2 + 1]);
    float4 h = ((float4*)g_h)[idx];
    float4 sc = ((const float4*)g_scale)[c4];
    float4 sh = ((const float4*)g_shift)[c4];
    h.x += fmaxf(o01.x * sc.x + sh.x, 0.f);
    h.y += fmaxf(o01.y * sc.y + sh.y, 0.f);
    h.z += fmaxf(o23.x * sc.z + sh.z, 0.f);
    h.w += fmaxf(o23.y * sc.w + sh.w, 0.f);
    ((float4*)g_h)[idx] = h;
    g_hbw[idx * 2 + 0] = pack_bf2(h.x, h.y);
    g_hbw[idx * 2 + 1] = pack_bf2(h.z, h.w);
}

// ---------------- fused edge MLP: W2 fully smem-resident ----------------
#define ETM 128
#define Z1S 132      // 132 % 32 == 4 -> conflict-free frag loads
#define EDGE_SMEM ((ETM * Z1S + 256 * Z1S) * 4 + 2 * ETM * 4 + 2 * ETM * 4)

__global__ void __launch_bounds__(256, 1) edge_kernel(
    const int* __restrict__ src, const int* __restrict__ dst,
    const unsigned* __restrict__ W2b, const float* __restrict__ b2,
    const float* __restrict__ W3, const float* __restrict__ b3,
    float* __restrict__ out)
{
    extern __shared__ unsigned smem[];
    unsigned* z12 = smem;                   // [ETM][Z1S]
    unsigned* Bs  = z12 + ETM * Z1S;        // [256][Z1S] full W2 in bf16x2
    float* part = (float*)(Bs + 256 * Z1S); // [2][ETM]
    int* se = (int*)(part + 2 * ETM);
    int* de = se + ETM;

    int tid = threadIdx.x;
    int lane = tid & 31, wid = tid >> 5;
    int warp_m = wid >> 1;
    int warp_n = wid & 1;
    int tg = lane & 3;
    int gid = lane >> 2;
    int eb = blockIdx.x * ETM;

    if (tid < ETM) {
        int e = eb + tid;
        se[tid] = (e < N_EDGES) ? src[e] : 0;
        de[tid] = (e < N_EDGES) ? dst[e] : 0;
    }
    // stage full W2 (256 rows x 32 uint4), coalesced LDG.128, conflict-free STS.128
#pragma unroll
    for (int it = 0; it < 32; it++) {
        int idx = it * 256 + tid;
        int n = idx >> 5;
        int kq = (idx & 31) * 4;
        uint4 v = *(const uint4*)&W2b[n * 128 + kq];
        *(uint4*)&Bs[n * Z1S + kq] = v;
    }
    __syncthreads();

    // phase A: z1 tile = relu(P[s]+Q[d])
#pragma unroll
    for (int it = 0; it < 64; it++) {
        int fid = it * 256 + tid;
        int i = fid >> 7;
        int w = fid & 127;
        unsigned p = g_Pbw[se[i] * 128 + w];
        unsigned q = g_Qbw[de[i] * 128 + w];
        z12[i * Z1S + w] = addrelu_bf2(p, q);
    }
    __syncthreads();

    // phase B: z2 = z1 @ W2^T — 16 k-steps, zero syncs
    float4 acc[2][16];
#pragma unroll
    for (int i = 0; i < 2; i++)
#pragma unroll
        for (int j = 0; j < 16; j++) acc[i][j] = make_float4(0.f, 0.f, 0.f, 0.f);

#pragma unroll
    for (int ks = 0; ks < 16; ks++) {
        int k2a = ks * 8;
        unsigned a[2][4];
#pragma unroll
        for (int i = 0; i < 2; i++) {
            int row = warp_m * 32 + i * 16 + gid;
            a[i][0] = z12[row * Z1S + k2a + tg];
            a[i][1] = z12[(row + 8) * Z1S + k2a + tg];
            a[i][2] = z12[row * Z1S + k2a + 4 + tg];
            a[i][3] = z12[(row + 8) * Z1S + k2a + 4 + tg];
        }
#pragma unroll
        for (int j = 0; j < 16; j++) {
            int col = warp_n * 128 + j * 8 + gid;
            unsigned b0 = Bs[col * Z1S + k2a + tg];
            unsigned b1 = Bs[col * Z1S + k2a + 4 + tg];
#pragma unroll
            for (int i = 0; i < 2; i++)
                mma_bf16(acc[i][j], a[i][0], a[i][1], a[i][2], a[i][3], b0, b1);
        }
    }

    // phase C: relu(z2+b2) . W3, reduce, sigmoid
    float res[2][2] = {{0.f, 0.f}, {0.f, 0.f}};
#pragma unroll
    for (int j = 0; j < 16; j++) {
        int col = warp_n * 128 + j * 8 + 2 * tg;
        float bb0 = b2[col],     w0 = W3[col];
        float bb1 = b2[col + 1], w1 = W3[col + 1];
#pragma unroll
        for (int i = 0; i < 2; i++) {
            res[i][0] += fmaxf(acc[i][j].x + bb0, 0.f) * w0
                       + fmaxf(acc[i][j].y + bb1, 0.f) * w1;
            res[i][1] += fmaxf(acc[i][j].z + bb0, 0.f) * w0
                       + fmaxf(acc[i][j].w + bb1, 0.f) * w1;
        }
    }
#pragma unroll
    for (int off = 1; off <= 2; off <<= 1) {
#pragma unroll
        for (int i = 0; i < 2; i++) {
            res[i][0] += __shfl_xor_sync(0xffffffffu, res[i][0], off);
            res[i][1] += __shfl_xor_sync(0xffffffffu, res[i][1], off);
        }
    }
    if (tg == 0) {
#pragma unroll
        for (int i = 0; i < 2; i++) {
            int row = warp_m * 32 + i * 16 + gid;
            part[warp_n * ETM + row] = res[i][0];
            part[warp_n * ETM + row + 8] = res[i][1];
        }
    }
    __syncthreads();
    if (tid < ETM) {
        int e = eb + tid;
        if (e < N_EDGES) {
            float v = part[tid] + part[ETM + tid] + b3[0];
            out[e] = 1.f / (1.f + expf(-v));
        }
    }
}

// ---------------- launcher ----------------
extern "C" void kernel_launch(void* const* d_in, const int* in_sizes, int n_in,
                              void* d_out, int out_size) {
    const float* x     = (const float*)d_in[0];
    const int*   ei    = (const int*)d_in[1];
    const float* Win   = (const float*)d_in[2];
    const float* Wrel  = (const float*)d_in[3];
    const float* brel  = (const float*)d_in[4];
    const float* Wroot = (const float*)d_in[5];
    const float* gamma = (const float*)d_in[6];
    const float* beta  = (const float*)d_in[7];
    const float* W1    = (const float*)d_in[8];
    const float* b1    = (const float*)d_in[9];
    const float* W2    = (const float*)d_in[10];
    const float* b2    = (const float*)d_in[11];
    const float* W3    = (const float*)d_in[12];
    const float* b3    = (const float*)d_in[13];
    float* out = (float*)d_out;
    const int* src = ei;
    const int* dst = ei + N_EDGES;

    unsigned *p_aggb, *p_hb, *p_outb, *p_Pb, *p_Qb, *p_Wb;
    cudaGetSymbolAddress((void**)&p_aggb, g_aggbw);
    cudaGetSymbolAddress((void**)&p_hb, g_hbw);
    cudaGetSymbolAddress((void**)&p_outb, g_outbw);
    cudaGetSymbolAddress((void**)&p_Pb, g_Pbw);
    cudaGetSymbolAddress((void**)&p_Qb, g_Qbw);
    cudaGetSymbolAddress((void**)&p_Wb, g_Wb);

    cudaFuncSetAttribute(edge_kernel, cudaFuncAttributeMaxDynamicSharedMemorySize, EDGE_SMEM);
    cudaFuncSetAttribute(tc_gemm_kernel, cudaFuncAttributeMaxDynamicSharedMemorySize, GEMM_SMEM);

    // weight pre-conversion to bf16
    convw_kernel<<<(LAYERS * 256 * 128 + 255) / 256, 256>>>(Wrel, p_Wb + WOFF_REL, 256, 0, LAYERS * 256 * 128);
    convw_kernel<<<(LAYERS * 256 * 128 + 255) / 256, 256>>>(Wroot, p_Wb + WOFF_ROOT, 256, 0, LAYERS * 256 * 128);
    convw_kernel<<<128, 256>>>(W1, p_Wb + WOFF_W1A, 512, 0, 32768);
    convw_kernel<<<128, 256>>>(W1, p_Wb + WOFF_W1B, 512, 256, 32768);
    convw_kernel<<<128, 256>>>(W2, p_Wb + WOFF_W2, 256, 0, 32768);

    // CSR build (+ stats zero)
    zero_int_kernel<<<(N_NODES + 255) / 256, 256>>>();
    count_kernel<<<(N_EDGES + 255) / 256, 256>>>(dst);
    scan_kernel<<<1, 1024>>>();
    fill_kernel<<<(N_EDGES + 255) / 256, 256>>>(src, dst);

    // input fc
    input_kernel<<<(N_NODES * 64 + 255) / 256, 256>>>(x, Win);

    dim3 ggrid(391, 2);
    for (int l = 0; l < LAYERS; l++) {
        agg_kernel<<<(N_NODES * 32 + 255) / 256, 256>>>();
        tc_gemm_kernel<<<ggrid, 256, GEMM_SMEM>>>(
            p_aggb, p_Wb + WOFF_REL + l * 32768,
            p_hb, p_Wb + WOFF_ROOT + l * 32768,
            brel + l * HID, p_outb, 1, 2);
        bnfinal_kernel<<<1, 256>>>(gamma + l * HID, beta + l * HID);
        bnapply_kernel<<<(N_NODES * 64 + 255) / 256, 256>>>();
    }

    // P = h@W1a^T + b1 ; Q = h@W1b^T
    tc_gemm_kernel<<<ggrid, 256, GEMM_SMEM>>>(p_hb, p_Wb + WOFF_W1A, nullptr, nullptr, b1, p_Pb, 0, 1);
    tc_gemm_kernel<<<ggrid, 256, GEMM_SMEM>>>(p_hb, p_Wb + WOFF_W1B, nullptr, nullptr, nullptr, p_Qb, 0, 1);

    // fused edge MLP
    edge_kernel<<<(N_EDGES + ETM - 1) / ETM, 256, EDGE_SMEM>>>(src, dst, p_Wb + WOFF_W2, b2, W3, b3, out);
}